// round 16
// baseline (speedup 1.0000x reference)
#include <cuda_runtime.h>
#include <cstdint>

// DiscreteAutoregressiveFlow: exact one-hot algebra over Z_257.
// next = (x_t * m[p] + c[p]) mod 257, per-state (m,c) from argmax of W[p]+b.
// Round 16: r14 skeleton. k_BC: uint2 table with 72B padded stride (no
// unpack, ~conflict-free LDS.64), prefix-composed maps (g_pre) so the last
// block's stitch is 8 LDS + 64 parallel L2 gathers instead of serial chains.

#define V        257
#define B        64
#define L        1024
#define SEGLEN   16
#define UNITS    8                        // segments per chain block
#define BPB      8                        // chain blocks per batch
#define CHAIN    (B * BPB)                // 512
#define REP      8                        // replicas per slot
#define STRIDE   9                        // uint2 per slot row (8 + 1 pad = 72B)
#define NST      258                      // states 0..256 plus 257 = ZERO
#define NSLOT    514                      // doubled-table slots
#define TABU2    (NSLOT * STRIDE)         // 4626 uint2 = 2313 uint4
#define TOTAL4   ((B * L * V) / 4)        // 4,214,784 uint4
#define TBLK     33                       // table blocks (264 warps >= 258)
#define MIXB     (TOTAL4 / 2048)          // 2058 blocks per stream role

// Slot convention: slot 0 = state 257 (ZERO/dead); slot s in [1,513] = state
// (s-1) mod 257. Step: z = x*m + c (alive z <= 65792); z mod 257 ==
// (z&255)-(z>>8) (mod 257); sl = lo-hi+258 in [1,513] alive, 0 for the dead
// trap (m=0, c=66048 -> hi=258). Branch-free.

__device__ __align__(16) uint2 g_tabRD[TABU2];           // padded doubled table
__device__ __align__(16) int   g_xidx[B * L];
__device__ __align__(16) uint4 g_pre[CHAIN * NST];       // 8 prefix exits/state
__device__ __align__(16) short g_bmap[CHAIN * NST];      // unit-7 (full block) map
__device__ int g_done[B];                                // zero-init; self-reset

// ---------------------------------------------------------------------------
// K_A: tables (33 blocks) + extract (read stream) + zero-fill (write stream).
// Table warps write the padded doubled uint2 table.
// ---------------------------------------------------------------------------
__global__ void __launch_bounds__(256) k_A(const float* __restrict__ W,
                                           const float* __restrict__ bb,
                                           const int*   __restrict__ inv_table,
                                           const uint4* __restrict__ x,
                                           uint4*       __restrict__ out) {
    int bid = blockIdx.x;
    int tid = threadIdx.x;

    if (bid < TBLK) {
        int p    = bid * 8 + (tid >> 5);
        int lane = tid & 31;
        if (p >= NST) return;
        const float* wrow = (p < V) ? (W + (size_t)p * (2 * V)) : nullptr;
        int bestj[2];
        #pragma unroll
        for (int h = 0; h < 2; h++) {
            float bv = -3.402823466e38f;
            int   bj = 0;
            for (int j = lane; j < V; j += 32) {
                int   col = h * V + j;
                float v   = bb[col] + (wrow ? wrow[col] : 0.0f);
                if (v > bv) { bv = v; bj = j; }     // first-max == jnp.argmax
            }
            #pragma unroll
            for (int off = 16; off; off >>= 1) {
                float ov = __shfl_down_sync(0xffffffffu, bv, off);
                int   oj = __shfl_down_sync(0xffffffffu, bj, off);
                if (ov > bv || (ov == bv && oj < bj)) { bv = ov; bj = oj; }
            }
            bestj[h] = bj;
        }
        unsigned mv = 0, cv = 0;
        if (lane == 0) {
            int l = bestj[0], s = bestj[1];
            int m = inv_table[s];                 // 0 iff s==0
            if (m != 0) { mv = (unsigned)m; cv = (unsigned)((V - (l * m) % V) % V); }
            else        { mv = 0u;          cv = 66048u; }   // dead trap -> slot 0
        }
        mv = __shfl_sync(0xffffffffu, mv, 0);
        cv = __shfl_sync(0xffffffffu, cv, 0);
        // state p -> slots: p<=255: p+1 and p+258; p==256: 257; p==257: 0.
        int slotA = (p == V) ? 0 : p + 1;
        if (lane < REP)
            g_tabRD[slotA * STRIDE + lane] = make_uint2(mv, cv);
        else if (lane < 2 * REP && p < 256)
            g_tabRD[(p + 258) * STRIDE + (lane - REP)] = make_uint2(mv, cv);
        return;
    }

    int mm   = bid - TBLK;
    int unit = mm >> 1;
    int base = unit * 2048 + tid;

    if (mm & 1) {
        uint4 z = make_uint4(0u, 0u, 0u, 0u);
        #pragma unroll
        for (int k = 0; k < 8; k++) out[base + k * 256] = z;
        return;
    }

    // extract: 8 coalesced uint4 loads front-batched (MLP_p1 = 8)
    uint4 v[8];
    #pragma unroll
    for (int k = 0; k < 8; k++) v[k] = x[base + k * 256];
    #pragma unroll
    for (int k = 0; k < 8; k++) {
        if (v[k].x | v[k].y | v[k].z | v[k].w) {
            unsigned a[4] = { v[k].x, v[k].y, v[k].z, v[k].w };
            int eb = (base + k * 256) * 4;
            #pragma unroll
            for (int j = 0; j < 4; j++) {
                if (a[j] != 0u) {
                    int idx = eb + j;
                    int row = idx / V;
                    g_xidx[row] = idx - row * V;
                }
            }
        }
    }
}

// ---------------------------------------------------------------------------
// K_BC: 512 blocks, one wave. Fill padded table (coalesced uint4), run 8
// chains/thread (+extra for states 256/257), compose prefix maps, publish.
// Last block per batch: smem block-entry walk + 64 parallel entry gathers +
// replay/scatter into the pre-zeroed output.
// ---------------------------------------------------------------------------
__global__ void __launch_bounds__(256) k_BC(float* __restrict__ out) {
    __shared__ __align__(16) uint2 tabP[TABU2];          // 37008 B
    __shared__ __align__(16) short segmapS[UNITS * NST]; // 4128 B (reused: bmaps)
    __shared__ __align__(16) int   sx[L];                // 4096 B (last block)
    __shared__ __align__(16) int   sxs[SEGLEN * UNITS];  // [t*8 + u]
    __shared__ short entryS[BPB * UNITS];
    __shared__ short blkentS[BPB];
    __shared__ int   isLast;

    int bid = blockIdx.x;
    int tid = threadIdx.x;
    int b   = bid / BPB;
    int blk = bid % BPB;

    // fill: 2313 uint4, fully coalesced
    {
        const uint4* src = (const uint4*)g_tabRD;
        uint4* dst = (uint4*)tabP;
        #pragma unroll
        for (int k = 0; k < 9; k++) dst[tid + k * 256] = src[tid + k * 256];
        if (tid < TABU2 / 2 - 2304) dst[2304 + tid] = src[2304 + tid];
    }
    if (tid < UNITS * SEGLEN) {
        int u = tid >> 4, t = tid & 15;
        sxs[t * 8 + u] = g_xidx[b * L + (blk * UNITS + u) * SEGLEN + t];
    }
    __syncthreads();

    // ---- segment maps: 8 branch-free chains/thread + extra on t<16 ----
    int rep = tid & (REP - 1);
    int xst = 256 + (tid & 1);          // extra-chain state (threads 0..15)
    int xun = (tid >> 1) & 7;           // extra-chain unit
    bool extra = (tid < 16);

    int slot[9];
    #pragma unroll
    for (int j = 0; j < 8; j++) slot[j] = tid + 1;       // state tid -> slot tid+1
    slot[8] = (xst == V) ? 0 : xst + 1;

    #pragma unroll
    for (int t = 0; t < SEGLEN; t++) {
        uint4 xv0 = *(const uint4*)&sxs[t * 8];
        uint4 xv1 = *(const uint4*)&sxs[t * 8 + 4];
        unsigned xs[8] = { xv0.x, xv0.y, xv0.z, xv0.w,
                           xv1.x, xv1.y, xv1.z, xv1.w };
        #pragma unroll
        for (int j = 0; j < 8; j++) {
            uint2 e = tabP[slot[j] * STRIDE + rep];      // LDS.64, ~no conflicts
            unsigned z = xs[j] * e.x + e.y;
            slot[j] = (int)(z & 255u) - (int)(z >> 8) + 258;
        }
        if (extra) {
            uint2 e = tabP[slot[8] * STRIDE + rep];
            unsigned z = (unsigned)sxs[t * 8 + xun] * e.x + e.y;
            slot[8] = (int)(z & 255u) - (int)(z >> 8) + 258;
        }
    }

    #pragma unroll
    for (int j = 0; j < 8; j++) {
        int s = slot[j];
        segmapS[j * NST + tid] =
            (short)((s == 0) ? V : ((s <= V) ? s - 1 : s - (V + 1)));
    }
    if (extra) {
        int s = slot[8];
        segmapS[xun * NST + xst] =
            (short)((s == 0) ? V : ((s <= V) ? s - 1 : s - (V + 1)));
    }
    __syncthreads();

    // ---- compose prefix maps (8 serial LDS per state), publish uint4 ----
    #pragma unroll
    for (int rr = 0; rr < 2; rr++) {
        int p = tid + rr * 256;
        if (p < NST) {
            unsigned short pr[8];
            int e = segmapS[p];
            pr[0] = (unsigned short)e;
            #pragma unroll
            for (int u = 1; u < UNITS; u++) {
                e = segmapS[u * NST + e];
                pr[u] = (unsigned short)e;
            }
            uint4 o;
            o.x = (unsigned)pr[0] | ((unsigned)pr[1] << 16);
            o.y = (unsigned)pr[2] | ((unsigned)pr[3] << 16);
            o.z = (unsigned)pr[4] | ((unsigned)pr[5] << 16);
            o.w = (unsigned)pr[6] | ((unsigned)pr[7] << 16);
            g_pre[(size_t)bid * NST + p] = o;
            g_bmap[(size_t)bid * NST + p] = (short)pr[7];
        }
    }
    __threadfence();
    __syncthreads();
    if (tid == 0) isLast = (atomicAdd(&g_done[b], 1) == BPB - 1);
    __syncthreads();
    if (!isLast) return;
    __threadfence();                                     // acquire peers' maps

    // ---- stitch: stage 8 block maps into smem (reuse segmapS), LDS walk ----
    ((uint4*)sx)[tid] = ((const uint4*)(g_xidx + b * L))[tid];  // batch x
    {
        const uint4* src = (const uint4*)(g_bmap + (size_t)(b * BPB) * NST);
        uint4* dst = (uint4*)segmapS;                    // 258 uint4
        dst[tid] = src[tid];
        if (tid < 2) dst[256 + tid] = src[256 + tid];
    }
    __syncthreads();
    if (tid == 0) {
        int st = V;                                      // ZERO
        #pragma unroll
        for (int k = 0; k < BPB; k++) {
            blkentS[k] = (short)st;
            st = segmapS[k * NST + st];                  // LDS chain
        }
        g_done[b] = 0;                                   // self-reset for replay
    }
    __syncthreads();
    if (tid < BPB * UNITS) {                             // 64 parallel gathers
        int k = tid >> 3, u = tid & 7;
        int ent = blkentS[k];
        int val;
        if (u == 0) val = ent;
        else {
            const unsigned short* pre =
                (const unsigned short*)&g_pre[(size_t)(b * BPB + k) * NST + ent];
            val = pre[u - 1];                            // exit of units 0..u-1
        }
        entryS[tid] = (short)val;
    }
    __syncthreads();

    // ---- replay + scatter: 64 threads, one 16-step chain each ----
    if (tid < BPB * UNITS) {
        int seg = tid;
        int ent = entryS[seg];
        int sl  = (ent == V) ? 0 : ent + 1;
        float* orow = out + (size_t)(b * L + seg * SEGLEN) * V;
        #pragma unroll
        for (int t = 0; t < SEGLEN; t++) {
            uint2 e = tabP[sl * STRIDE + (tid & 7)];
            unsigned z = (unsigned)sx[seg * SEGLEN + t] * e.x + e.y;
            sl = (int)(z & 255u) - (int)(z >> 8) + 258;
            if (sl != 0) {
                int oi = (sl <= V) ? sl - 1 : sl - (V + 1);
                orow[(size_t)t * V + oi] = 1.0f;
            }
        }
    }
}

// ---------------------------------------------------------------------------
extern "C" void kernel_launch(void* const* d_in, const int* in_sizes, int n_in,
                              void* d_out, int out_size) {
    const float* x   = (const float*)d_in[0];   // [B, L, V] f32
    const float* W   = (const float*)d_in[1];   // [V, 2V]   f32
    const float* bb  = (const float*)d_in[2];   // [2V]      f32
    const int*   inv = (const int*)  d_in[3];   // [V]       i32

    k_A<<<TBLK + 2 * MIXB, 256>>>(W, bb, inv, (const uint4*)x, (uint4*)d_out);
    k_BC<<<CHAIN, 256>>>((float*)d_out);
}